// round 5
// baseline (speedup 1.0000x reference)
#include <cuda_runtime.h>
#include <math.h>
#include <stdint.h>

// CRF loss: L=512 seq, B=512 batch, T=128 tags.
#define LL 512
#define BB 512
#define TT 128
#define NB 4              // batches per CTA (2 groups x 2)
#define NCTA (BB/NB)      // 128 CTAs, 1 per SM
#define NTHREADS 512
#define PQ 36             // padded quarter stride (floats) — kills 4-way LDS conflicts
#define PB (4*PQ)         // padded per-batch alpha row = 144 floats
#define LN2F 0.6931471805599453f

__device__ float g_logZ[BB];
__device__ float g_num[BB];

union F4U { float4 v; struct { unsigned long long p01, p23; } u; };

__device__ __forceinline__ unsigned long long ffma2(unsigned long long a,
                                                    unsigned long long b,
                                                    unsigned long long c) {
    unsigned long long d;
    asm("fma.rn.f32x2 %0, %1, %2, %3;" : "=l"(d) : "l"(a), "l"(b), "l"(c));
    return d;
}
__device__ __forceinline__ unsigned long long packf2(float lo, float hi) {
    unsigned long long r;
    asm("mov.b64 %0, {%1,%2};" : "=l"(r) : "f"(lo), "f"(hi));
    return r;
}
__device__ __forceinline__ float2 unpackf2(unsigned long long v) {
    float2 f;
    asm("mov.b64 {%0,%1}, %2;" : "=f"(f.x), "=f"(f.y) : "l"(v));
    return f;
}
__device__ __forceinline__ void barg(int g) {   // named barrier per 256-thread group
    asm volatile("bar.sync %0, 256;" :: "r"(g + 1));
}

// Org: 16 warps. g = w>>3 (group: 2 batches). wg = w&7 covers k in [wg*16, wg*16+16).
// lane: jo = lane>>3 (j-quarter of 32), kidx = lane&7 -> k0 = wg*16 + kidx*2.
// Lane tile: 32 j x 2 k x 2 b = 128 MACs = 64 FFMA2/step. E register-resident (64 regs).
__global__ __launch_bounds__(NTHREADS, 1)
void crf_forward(const float* __restrict__ emissions,
                 const int* __restrict__ mask,
                 const float* __restrict__ start_t,
                 const float* __restrict__ end_t,
                 const float* __restrict__ trans)
{
    __shared__ __align__(16) float sP[2][2][2][PB];   // [ping][g][b][k padded quarters]
    __shared__ __align__(16) float sS[2][2][2][8];    // [ping][g][b][wg] partials

    const int tid  = threadIdx.x;
    const int w    = tid >> 5;
    const int lane = tid & 31;
    const int g    = w >> 3;
    const int wg   = w & 7;
    const int jo   = lane >> 3;        // j-quarter 0..3
    const int kidx = lane & 7;
    const int k0   = wg * 16 + kidx * 2;
    const int lb   = jo & 1;           // this lane's local batch
    const int bg   = blockIdx.x * NB + g * 2 + lb;
    const int ka   = (k0 >> 5) * PQ + (k0 & 31);      // padded alpha offset of k0

    // ---- E = exp(transitions): 32 j x 2 k per lane, fully in registers ----
    unsigned long long eR[8][2][2];    // [t][sub jpair][k col]
    #pragma unroll
    for (int t = 0; t < 8; ++t) {
        #pragma unroll
        for (int sub = 0; sub < 2; ++sub) {
            int j = jo * 32 + t * 4 + sub * 2;
            eR[t][sub][0] = packf2(__expf(trans[j * TT + k0]),
                                   __expf(trans[(j + 1) * TT + k0]));
            eR[t][sub][1] = packf2(__expf(trans[j * TT + k0 + 1]),
                                   __expf(trans[(j + 1) * TT + k0 + 1]));
        }
    }

    // ---- init: p~0 = exp(start + emissions[0]) ----
    {
        const float2 em = *(const float2*)(emissions + (size_t)bg * TT + k0);
        const float2 st = *(const float2*)(start_t + k0);
        float v0 = __expf(st.x + em.x);
        float v1 = __expf(st.y + em.y);
        if (jo < 2)
            *(float2*)&sP[0][g][lb][ka] = make_float2(v0, v1);
        float pr = v0 + v1;
        pr += __shfl_xor_sync(0xffffffffu, pr, 1);
        pr += __shfl_xor_sync(0xffffffffu, pr, 2);
        pr += __shfl_xor_sync(0xffffffffu, pr, 4);
        if (kidx == 0 && jo < 2) sS[0][g][lb][wg] = pr;
    }
    __syncthreads();

    int cur = 0;
    int e_acc = 0;

    for (int i = 1; i < LL; ++i) {
        const float* P0 = &sP[cur][g][0][0];
        const float* P1 = &sP[cur][g][1][0];

        // prefetch (consumed late; hidden under FMA)
        const float2 em   = *(const float2*)(emissions + ((size_t)i * BB + bg) * TT + k0);
        const int    m    = mask[i * BB + bg];
        const float2 oldp = *(const float2*)&sP[cur][g][lb][ka];
        const float4 sva  = *(const float4*)&sS[cur][g][lb][0];
        const float4 svb  = *(const float4*)&sS[cur][g][lb][4];

        // pending exact power-of-two scale from previous step
        float s = ((sva.x + sva.y) + (sva.z + sva.w)) + ((svb.x + svb.y) + (svb.z + svb.w));
        int   e = ((__float_as_int(s) >> 23) & 255) - 126;    // s*2^-e in [0.5,1)
        float scale = __int_as_float((127 - e) << 23);

        // ---- j-contraction over this lane's 32-j quarter (padded, conflict-free) ----
        unsigned long long acc00 = 0, acc01 = 0, acc10 = 0, acc11 = 0;
        const int jb = jo * PQ;
        #pragma unroll
        for (int t = 0; t < 8; ++t) {
            F4U p0; p0.v = *(const float4*)(P0 + jb + t * 4);
            F4U p1; p1.v = *(const float4*)(P1 + jb + t * 4);
            acc00 = ffma2(p0.u.p01, eR[t][0][0], acc00);
            acc01 = ffma2(p0.u.p01, eR[t][0][1], acc01);
            acc10 = ffma2(p1.u.p01, eR[t][0][0], acc10);
            acc11 = ffma2(p1.u.p01, eR[t][0][1], acc11);
            acc00 = ffma2(p0.u.p23, eR[t][1][0], acc00);
            acc01 = ffma2(p0.u.p23, eR[t][1][1], acc01);
            acc10 = ffma2(p1.u.p23, eR[t][1][0], acc10);
            acc11 = ffma2(p1.u.p23, eR[t][1][1], acc11);
        }

        // horizontal add + reduce over jo quarters (lanes ^8, ^16)
        float2 h;
        h = unpackf2(acc00); float f00 = h.x + h.y;
        h = unpackf2(acc01); float f01 = h.x + h.y;
        h = unpackf2(acc10); float f10 = h.x + h.y;
        h = unpackf2(acc11); float f11 = h.x + h.y;
        f00 += __shfl_xor_sync(0xffffffffu, f00, 8);
        f01 += __shfl_xor_sync(0xffffffffu, f01, 8);
        f10 += __shfl_xor_sync(0xffffffffu, f10, 8);
        f11 += __shfl_xor_sync(0xffffffffu, f11, 8);
        f00 += __shfl_xor_sync(0xffffffffu, f00, 16);
        f01 += __shfl_xor_sync(0xffffffffu, f01, 16);
        f10 += __shfl_xor_sync(0xffffffffu, f10, 16);
        f11 += __shfl_xor_sync(0xffffffffu, f11, 16);

        // lane's batch (lb): pick matching accumulators
        float q0 = lb ? f10 : f00;
        float q1 = lb ? f11 : f01;

        float qs0, qs1;
        if (m) {
            qs0 = q0 * (__expf(em.x) * scale);
            qs1 = q1 * (__expf(em.y) * scale);
            e_acc += e;
        } else {
            qs0 = oldp.x; qs1 = oldp.y;
        }

        if (jo < 2)
            *(float2*)&sP[cur ^ 1][g][lb][ka] = make_float2(qs0, qs1);

        float pr = qs0 + qs1;
        pr += __shfl_xor_sync(0xffffffffu, pr, 1);
        pr += __shfl_xor_sync(0xffffffffu, pr, 2);
        pr += __shfl_xor_sync(0xffffffffu, pr, 4);
        if (kidx == 0 && jo < 2) sS[cur ^ 1][g][lb][wg] = pr;

        barg(g);               // group-private barrier; other group overlaps our tail
        cur ^= 1;
    }

    // ---- finalize: logZ = e_acc*ln2 + log( sum_k p~[k]*exp(end[k]) ) ----
    {
        const float2 en = *(const float2*)(end_t + k0);
        const float2 pv = *(const float2*)&sP[cur][g][lb][ka];
        float z = pv.x * __expf(en.x) + pv.y * __expf(en.y);
        z += __shfl_xor_sync(0xffffffffu, z, 1);
        z += __shfl_xor_sync(0xffffffffu, z, 2);
        z += __shfl_xor_sync(0xffffffffu, z, 4);
        if (kidx == 0 && jo < 2) sS[0][g][lb][wg] = z;
        barg(g);
        if (wg == 0 && kidx == 0 && jo < 2) {
            float tot = 0.f;
            #pragma unroll
            for (int ww = 0; ww < 8; ++ww) tot += sS[0][g][lb][ww];
            g_logZ[bg] = (float)e_acc * LN2F + logf(tot);
        }
    }
}

// Numerator: one block per batch.
__global__ void crf_num(const float* __restrict__ emissions,
                        const int*   __restrict__ tags,
                        const int*   __restrict__ mask,
                        const float* __restrict__ start_t,
                        const float* __restrict__ end_t,
                        const float* __restrict__ trans)
{
    const int b   = blockIdx.x;
    const int tid = threadIdx.x;
    __shared__ float rf[256];
    __shared__ int   ri[256];

    float loc = 0.f;
    int   cnt = 0;
    for (int i = tid; i < LL; i += 256) {
        int tag = tags[i * BB + b];
        int m   = mask[i * BB + b];
        if (m) {
            loc += emissions[((size_t)i * BB + b) * TT + tag];
            cnt++;
            if (i > 0) loc += trans[tags[(i - 1) * BB + b] * TT + tag];
        }
        if (i == 0) loc += start_t[tag];
    }
    rf[tid] = loc; ri[tid] = cnt;
    __syncthreads();
    #pragma unroll
    for (int s = 128; s > 0; s >>= 1) {
        if (tid < s) { rf[tid] += rf[tid + s]; ri[tid] += ri[tid + s]; }
        __syncthreads();
    }
    if (tid == 0) {
        int ends = ri[0] - 1;
        if (ends < 0) ends = 0;
        g_num[b] = rf[0] + end_t[tags[ends * BB + b]];
    }
}

__global__ void crf_final(float* __restrict__ out)
{
    __shared__ float r[512];
    const int tid = threadIdx.x;
    r[tid] = g_logZ[tid] - g_num[tid];
    __syncthreads();
    #pragma unroll
    for (int s = 256; s > 0; s >>= 1) {
        if (tid < s) r[tid] += r[tid + s];
        __syncthreads();
    }
    if (tid == 0) out[0] = r[0] * (1.0f / (float)BB);
}

extern "C" void kernel_launch(void* const* d_in, const int* in_sizes, int n_in,
                              void* d_out, int out_size)
{
    const float* emissions = (const float*)d_in[0];
    const int*   tags      = (const int*)d_in[1];
    const int*   mask      = (const int*)d_in[2];
    const float* start_t   = (const float*)d_in[3];
    const float* end_t     = (const float*)d_in[4];
    const float* trans     = (const float*)d_in[5];
    float*       out       = (float*)d_out;

    crf_forward<<<NCTA, NTHREADS>>>(emissions, mask, start_t, end_t, trans);
    crf_num<<<BB, 256>>>(emissions, tags, mask, start_t, end_t, trans);
    crf_final<<<1, BB>>>(out);
}

// round 6
// speedup vs baseline: 1.0121x; 1.0121x over previous
#include <cuda_runtime.h>
#include <math.h>
#include <stdint.h>

// CRF loss: L=512 seq, B=512 batch, T=128 tags.
#define LL 512
#define BB 512
#define TT 128
#define NB 4              // batches per CTA, all warps cooperate on all 4
#define NCTA (BB/NB)      // 128 CTAs, 1/SM
#define NTHREADS 256
#define PQ 36             // padded j-quarter stride (floats)
#define PB (4*PQ)         // padded per-batch alpha row = 144 floats
#define LN2F 0.6931471805599453f

__device__ float g_logZ[BB];
__device__ float g_num[BB];

union F4U { float4 v; struct { unsigned long long p01, p23; } u; };

__device__ __forceinline__ unsigned long long ffma2(unsigned long long a,
                                                    unsigned long long b,
                                                    unsigned long long c) {
    unsigned long long d;
    asm("fma.rn.f32x2 %0, %1, %2, %3;" : "=l"(d) : "l"(a), "l"(b), "l"(c));
    return d;
}
__device__ __forceinline__ unsigned long long packf2(float lo, float hi) {
    unsigned long long r;
    asm("mov.b64 %0, {%1,%2};" : "=l"(r) : "f"(lo), "f"(hi));
    return r;
}
__device__ __forceinline__ float2 unpackf2(unsigned long long v) {
    float2 f;
    asm("mov.b64 {%0,%1}, %2;" : "=f"(f.x), "=f"(f.y) : "l"(v));
    return f;
}

// Org: 8 warps. Lane: jq = lane>>3 (j-quarter AND epilogue batch), kidx = lane&7,
// k0 = w*16 + kidx*2. Lane tile: 32j x 2k x 4b = 128 FFMA2/step. E: 32 u64 regs.
__global__ __launch_bounds__(NTHREADS, 1)
void crf_forward(const float* __restrict__ emissions,
                 const int* __restrict__ mask,
                 const float* __restrict__ start_t,
                 const float* __restrict__ end_t,
                 const float* __restrict__ trans)
{
    __shared__ __align__(16) float sP[2][NB][PB];   // [ping][b][k padded by quarter]
    __shared__ __align__(16) float sZ[NB][8];       // final-reduce partials

    const int tid  = threadIdx.x;
    const int w    = tid >> 5;
    const int lane = tid & 31;
    const int jq   = lane >> 3;        // j-quarter; also this lane's epilogue batch
    const int kidx = lane & 7;
    const int k0   = w * 16 + kidx * 2;
    const int bg   = blockIdx.x * NB + jq;
    const int ka   = (k0 >> 5) * PQ + (k0 & 31);    // padded alpha offset of k0
    const int jb   = jq * PQ;                       // padded offset of this j-quarter

    // ---- E = exp(transitions): 32 j x 2 k per lane, register-resident ----
    unsigned long long eR[8][2][2];    // [t][j-subpair][k col]
    #pragma unroll
    for (int t = 0; t < 8; ++t) {
        #pragma unroll
        for (int sub = 0; sub < 2; ++sub) {
            int j = jq * 32 + t * 4 + sub * 2;
            eR[t][sub][0] = packf2(__expf(trans[j * TT + k0]),
                                   __expf(trans[(j + 1) * TT + k0]));
            eR[t][sub][1] = packf2(__expf(trans[j * TT + k0 + 1]),
                                   __expf(trans[(j + 1) * TT + k0 + 1]));
        }
    }

    // ---- init: p~0 = exp(start + emissions[0]) for (batch jq, tags k0,k0+1) ----
    {
        const float2 em = *(const float2*)(emissions + (size_t)bg * TT + k0);
        const float2 st = *(const float2*)(start_t + k0);
        *(float2*)&sP[0][jq][ka] = make_float2(__expf(st.x + em.x),
                                               __expf(st.y + em.y));
    }
    __syncthreads();

    int cur = 0;
    int e_acc = 0;

    for (int i = 1; i < LL; ++i) {
        const float* Pin = &sP[cur][0][0];

        // prologue (off FMA critical path): emissions, mask, pass-through p,
        // and the scale estimate from p'[jq][0..3] of the previous step.
        const float2 em   = *(const float2*)(emissions + ((size_t)i * BB + bg) * TT + k0);
        const int    m    = mask[i * BB + bg];
        const float2 oldp = *(const float2*)&sP[cur][jq][ka];
        const float4 est  = *(const float4*)&sP[cur][jq][0];

        float s = (est.x + est.y) + (est.z + est.w);
        int   e = ((__float_as_int(s) >> 23) & 255) - 126;   // s*2^-e in [0.5,1)
        float scale = __int_as_float((127 - e) << 23);       // exact 2^-e

        // ---- j-contraction: 8 independent chains (4 batches x 2 k) ----
        unsigned long long acc[NB][2];
        #pragma unroll
        for (int b = 0; b < NB; ++b) { acc[b][0] = 0ull; acc[b][1] = 0ull; }

        #pragma unroll
        for (int t = 0; t < 8; ++t) {
            #pragma unroll
            for (int b = 0; b < NB; ++b) {
                F4U pv; pv.v = *(const float4*)(Pin + b * PB + jb + t * 4);
                acc[b][0] = ffma2(pv.u.p01, eR[t][0][0], acc[b][0]);
                acc[b][1] = ffma2(pv.u.p01, eR[t][0][1], acc[b][1]);
                acc[b][0] = ffma2(pv.u.p23, eR[t][1][0], acc[b][0]);
                acc[b][1] = ffma2(pv.u.p23, eR[t][1][1], acc[b][1]);
            }
        }

        // horizontal add, then reduce the 4 j-quarters (shfl ^8, ^16)
        float f0[NB], f1[NB];
        #pragma unroll
        for (int b = 0; b < NB; ++b) {
            float2 h0 = unpackf2(acc[b][0]); f0[b] = h0.x + h0.y;
            float2 h1 = unpackf2(acc[b][1]); f1[b] = h1.x + h1.y;
        }
        #pragma unroll
        for (int b = 0; b < NB; ++b) {
            f0[b] += __shfl_xor_sync(0xffffffffu, f0[b], 8);
            f1[b] += __shfl_xor_sync(0xffffffffu, f1[b], 8);
            f0[b] += __shfl_xor_sync(0xffffffffu, f0[b], 16);
            f1[b] += __shfl_xor_sync(0xffffffffu, f1[b], 16);
        }

        // lane keeps batch b == jq
        float q0 = (jq < 2) ? (jq == 0 ? f0[0] : f0[1]) : (jq == 2 ? f0[2] : f0[3]);
        float q1 = (jq < 2) ? (jq == 0 ? f1[0] : f1[1]) : (jq == 2 ? f1[2] : f1[3]);

        float qs0, qs1;
        if (m) {
            qs0 = q0 * (__expf(em.x) * scale);
            qs1 = q1 * (__expf(em.y) * scale);
            e_acc += e;
        } else {
            qs0 = oldp.x; qs1 = oldp.y;
        }

        *(float2*)&sP[cur ^ 1][jq][ka] = make_float2(qs0, qs1);

        __syncthreads();
        cur ^= 1;
    }

    // ---- finalize: logZ = e_acc*ln2 + log( sum_k p~[k]*exp(end[k]) ) ----
    {
        const float2 en = *(const float2*)(end_t + k0);
        const float2 pv = *(const float2*)&sP[cur][jq][ka];
        float z = pv.x * __expf(en.x) + pv.y * __expf(en.y);
        z += __shfl_xor_sync(0xffffffffu, z, 1);
        z += __shfl_xor_sync(0xffffffffu, z, 2);
        z += __shfl_xor_sync(0xffffffffu, z, 4);
        if (kidx == 0) sZ[jq][w] = z;
        __syncthreads();
        if (w == 0 && kidx == 0) {
            float tot = 0.f;
            #pragma unroll
            for (int ww = 0; ww < 8; ++ww) tot += sZ[jq][ww];
            g_logZ[bg] = (float)e_acc * LN2F + logf(tot);
        }
    }
}

// Numerator: one block per batch.
__global__ void crf_num(const float* __restrict__ emissions,
                        const int*   __restrict__ tags,
                        const int*   __restrict__ mask,
                        const float* __restrict__ start_t,
                        const float* __restrict__ end_t,
                        const float* __restrict__ trans)
{
    const int b   = blockIdx.x;
    const int tid = threadIdx.x;
    __shared__ float rf[256];
    __shared__ int   ri[256];

    float loc = 0.f;
    int   cnt = 0;
    for (int i = tid; i < LL; i += 256) {
        int tag = tags[i * BB + b];
        int m   = mask[i * BB + b];
        if (m) {
            loc += emissions[((size_t)i * BB + b) * TT + tag];
            cnt++;
            if (i > 0) loc += trans[tags[(i - 1) * BB + b] * TT + tag];
        }
        if (i == 0) loc += start_t[tag];
    }
    rf[tid] = loc; ri[tid] = cnt;
    __syncthreads();
    #pragma unroll
    for (int s = 128; s > 0; s >>= 1) {
        if (tid < s) { rf[tid] += rf[tid + s]; ri[tid] += ri[tid + s]; }
        __syncthreads();
    }
    if (tid == 0) {
        int ends = ri[0] - 1;
        if (ends < 0) ends = 0;
        g_num[b] = rf[0] + end_t[tags[ends * BB + b]];
    }
}

__global__ void crf_final(float* __restrict__ out)
{
    __shared__ float r[512];
    const int tid = threadIdx.x;
    r[tid] = g_logZ[tid] - g_num[tid];
    __syncthreads();
    #pragma unroll
    for (int s = 256; s > 0; s >>= 1) {
        if (tid < s) r[tid] += r[tid + s];
        __syncthreads();
    }
    if (tid == 0) out[0] = r[0] * (1.0f / (float)BB);
}

extern "C" void kernel_launch(void* const* d_in, const int* in_sizes, int n_in,
                              void* d_out, int out_size)
{
    const float* emissions = (const float*)d_in[0];
    const int*   tags      = (const int*)d_in[1];
    const int*   mask      = (const int*)d_in[2];
    const float* start_t   = (const float*)d_in[3];
    const float* end_t     = (const float*)d_in[4];
    const float* trans     = (const float*)d_in[5];
    float*       out       = (float*)d_out;

    crf_forward<<<NCTA, NTHREADS>>>(emissions, mask, start_t, end_t, trans);
    crf_num<<<BB, 256>>>(emissions, tags, mask, start_t, end_t, trans);
    crf_final<<<1, BB>>>(out);
}

// round 7
// speedup vs baseline: 1.0784x; 1.0655x over previous
#include <cuda_runtime.h>
#include <math.h>
#include <stdint.h>

// CRF loss: L=512 seq, B=512 batch, T=128 tags.
#define LL 512
#define BB 512
#define TT 128
#define NB 4              // batches per CTA
#define NCTA (BB/NB)      // 128 CTAs, 1/SM
#define NTHREADS 256
#define LN2F 0.6931471805599453f

__device__ float g_logZ[BB];
__device__ float g_num[BB];

union F4U { float4 v; struct { unsigned long long p01, p23; } u; };

__device__ __forceinline__ unsigned long long ffma2(unsigned long long a,
                                                    unsigned long long b,
                                                    unsigned long long c) {
    unsigned long long d;
    asm("fma.rn.f32x2 %0, %1, %2, %3;" : "=l"(d) : "l"(a), "l"(b), "l"(c));
    return d;
}
__device__ __forceinline__ unsigned long long packf2(float lo, float hi) {
    unsigned long long r;
    asm("mov.b64 %0, {%1,%2};" : "=l"(r) : "f"(lo), "f"(hi));
    return r;
}
__device__ __forceinline__ float2 unpackf2(unsigned long long v) {
    float2 f;
    asm("mov.b64 {%0,%1}, %2;" : "=f"(f.x), "=f"(f.y) : "l"(v));
    return f;
}

// Org: 8 warps, 256 lanes. gk = w*32+lane; kk = gk&127 (this lane's k-column),
// bp = gk>>7 (batch pair). Lane computes p'[b][kk] for b in {2bp, 2bp+1} with the
// FULL 128-j dot product in-register -> NO cross-lane shuffles in the recursion.
// E: one k-column = 64 u64 regs.
__global__ __launch_bounds__(NTHREADS, 1)
void crf_forward(const float* __restrict__ emissions,
                 const int* __restrict__ mask,
                 const float* __restrict__ start_t,
                 const float* __restrict__ end_t,
                 const float* __restrict__ trans)
{
    __shared__ __align__(16) float sP[2][NB][TT];   // [ping][b][k]
    __shared__ __align__(16) float sZf[NB][TT];     // final-reduce partials
    __shared__ int sEa[NB];

    const int tid  = threadIdx.x;
    const int w    = tid >> 5;
    const int lane = tid & 31;
    const int gk   = w * 32 + lane;
    const int kk   = gk & 127;
    const int bp   = gk >> 7;          // 0 or 1
    const int b0l  = bp * 2;
    const int b1l  = bp * 2 + 1;
    const int gb0  = blockIdx.x * NB + b0l;
    const int gb1  = gb0 + 1;

    // ---- E column kk: E[j][kk] = exp(trans[j][kk]), packed over j-pairs ----
    unsigned long long eR[64];
    #pragma unroll
    for (int t = 0; t < 64; ++t)
        eR[t] = packf2(__expf(trans[(2 * t) * TT + kk]),
                       __expf(trans[(2 * t + 1) * TT + kk]));

    // ---- init p~0 = exp(start + emissions[0]) ----
    {
        float st = start_t[kk];
        sP[0][b0l][kk] = __expf(st + emissions[(size_t)gb0 * TT + kk]);
        sP[0][b1l][kk] = __expf(st + emissions[(size_t)gb1 * TT + kk]);
    }
    __syncthreads();

    int cur = 0;
    int eA = 0, eB = 0;

    // software-prefetched emissions/mask for step i=1
    float emA = emissions[((size_t)1 * BB + gb0) * TT + kk];
    float emB = emissions[((size_t)1 * BB + gb1) * TT + kk];
    int   mA  = mask[1 * BB + gb0];
    int   mB  = mask[1 * BB + gb1];

    for (int i = 1; i < LL; ++i) {
        const float* P0 = &sP[cur][b0l][0];
        const float* P1 = &sP[cur][b1l][0];
        float*       Q0 = &sP[cur ^ 1][b0l][0];
        float*       Q1 = &sP[cur ^ 1][b1l][0];

        // est-based exact power-of-2 scale per batch (broadcast LDS, off critical path)
        const float4 ev0 = *(const float4*)&P0[0];
        const float4 ev1 = *(const float4*)&P1[0];
        float sA = (ev0.x + ev0.y) + (ev0.z + ev0.w);
        float sB = (ev1.x + ev1.y) + (ev1.z + ev1.w);
        int   esA = ((__float_as_int(sA) >> 23) & 255) - 126;
        int   esB = ((__float_as_int(sB) >> 23) & 255) - 126;
        float scA = __int_as_float((127 - esA) << 23);
        float scB = __int_as_float((127 - esB) << 23);
        float fA0 = __expf(emA) * scA;          // factor ready long before FMA ends
        float fB0 = __expf(emB) * scB;
        float oldA = P0[kk];
        float oldB = P1[kk];

        // prefetch next step's emissions/mask (clamped; dead after last iter)
        int inx = (i + 1 < LL) ? i + 1 : LL - 1;
        float nemA = emissions[((size_t)inx * BB + gb0) * TT + kk];
        float nemB = emissions[((size_t)inx * BB + gb1) * TT + kk];
        int   nmA  = mask[inx * BB + gb0];
        int   nmB  = mask[inx * BB + gb1];

        // ---- full 128-j dot product, 4 independent FFMA2 chains ----
        unsigned long long a00 = 0, a01 = 0, a10 = 0, a11 = 0;
        #pragma unroll
        for (int t = 0; t < 32; ++t) {
            F4U p0; p0.v = *(const float4*)(P0 + t * 4);   // broadcast within warp
            F4U p1; p1.v = *(const float4*)(P1 + t * 4);
            a00 = ffma2(p0.u.p01, eR[2 * t],     a00);
            a01 = ffma2(p0.u.p23, eR[2 * t + 1], a01);
            a10 = ffma2(p1.u.p01, eR[2 * t],     a10);
            a11 = ffma2(p1.u.p23, eR[2 * t + 1], a11);
        }
        float2 h0 = unpackf2(a00), h1 = unpackf2(a01);
        float2 h2 = unpackf2(a10), h3 = unpackf2(a11);
        float qA = (h0.x + h0.y) + (h1.x + h1.y);
        float qB = (h2.x + h2.y) + (h3.x + h3.y);

        float outA, outB;
        if (mA) { outA = qA * fA0; eA += esA; } else outA = oldA;
        if (mB) { outB = qB * fB0; eB += esB; } else outB = oldB;

        Q0[kk] = outA;
        Q1[kk] = outB;

        emA = nemA; emB = nemB; mA = nmA; mB = nmB;

        __syncthreads();
        cur ^= 1;
    }

    // ---- finalize: logZ_b = e_acc*ln2 + log( sum_k p~[k]*exp(end[k]) ) ----
    {
        float enk = __expf(end_t[kk]);
        sZf[b0l][kk] = sP[cur][b0l][kk] * enk;
        sZf[b1l][kk] = sP[cur][b1l][kk] * enk;
        if (kk == 0) { sEa[b0l] = eA; sEa[b1l] = eB; }
    }
    __syncthreads();
    if (w == 0) {
        #pragma unroll
        for (int b = 0; b < NB; ++b) {
            float v = sZf[b][lane] + sZf[b][lane + 32]
                    + sZf[b][lane + 64] + sZf[b][lane + 96];
            v += __shfl_xor_sync(0xffffffffu, v, 1);
            v += __shfl_xor_sync(0xffffffffu, v, 2);
            v += __shfl_xor_sync(0xffffffffu, v, 4);
            v += __shfl_xor_sync(0xffffffffu, v, 8);
            v += __shfl_xor_sync(0xffffffffu, v, 16);
            if (lane == 0)
                g_logZ[blockIdx.x * NB + b] = (float)sEa[b] * LN2F + logf(v);
        }
    }
}

// Numerator: one block per batch.
__global__ void crf_num(const float* __restrict__ emissions,
                        const int*   __restrict__ tags,
                        const int*   __restrict__ mask,
                        const float* __restrict__ start_t,
                        const float* __restrict__ end_t,
                        const float* __restrict__ trans)
{
    const int b   = blockIdx.x;
    const int tid = threadIdx.x;
    __shared__ float rf[256];
    __shared__ int   ri[256];

    float loc = 0.f;
    int   cnt = 0;
    for (int i = tid; i < LL; i += 256) {
        int tag = tags[i * BB + b];
        int m   = mask[i * BB + b];
        if (m) {
            loc += emissions[((size_t)i * BB + b) * TT + tag];
            cnt++;
            if (i > 0) loc += trans[tags[(i - 1) * BB + b] * TT + tag];
        }
        if (i == 0) loc += start_t[tag];
    }
    rf[tid] = loc; ri[tid] = cnt;
    __syncthreads();
    #pragma unroll
    for (int s = 128; s > 0; s >>= 1) {
        if (tid < s) { rf[tid] += rf[tid + s]; ri[tid] += ri[tid + s]; }
        __syncthreads();
    }
    if (tid == 0) {
        int ends = ri[0] - 1;
        if (ends < 0) ends = 0;
        g_num[b] = rf[0] + end_t[tags[ends * BB + b]];
    }
}

__global__ void crf_final(float* __restrict__ out)
{
    __shared__ float r[512];
    const int tid = threadIdx.x;
    r[tid] = g_logZ[tid] - g_num[tid];
    __syncthreads();
    #pragma unroll
    for (int s = 256; s > 0; s >>= 1) {
        if (tid < s) r[tid] += r[tid + s];
        __syncthreads();
    }
    if (tid == 0) out[0] = r[0] * (1.0f / (float)BB);
}

extern "C" void kernel_launch(void* const* d_in, const int* in_sizes, int n_in,
                              void* d_out, int out_size)
{
    const float* emissions = (const float*)d_in[0];
    const int*   tags      = (const int*)d_in[1];
    const int*   mask      = (const int*)d_in[2];
    const float* start_t   = (const float*)d_in[3];
    const float* end_t     = (const float*)d_in[4];
    const float* trans     = (const float*)d_in[5];
    float*       out       = (float*)d_out;

    crf_forward<<<NCTA, NTHREADS>>>(emissions, mask, start_t, end_t, trans);
    crf_num<<<BB, 256>>>(emissions, tags, mask, start_t, end_t, trans);
    crf_final<<<1, BB>>>(out);
}

// round 8
// speedup vs baseline: 1.5024x; 1.3932x over previous
#include <cuda_runtime.h>
#include <math.h>
#include <stdint.h>

// CRF loss: L=512 seq, B=512 batch, T=128 tags.
#define LL 512
#define BB 512
#define TT 128
#define NBC 2             // batches per CTA
#define NCTA (BB/NBC)     // 256 CTAs -> 2 CTAs/SM (independent phase domains)
#define NTHREADS 256
#define PQ 36             // padded j-quarter stride (floats)
#define PB (4*PQ)         // padded per-batch alpha row
#define LN2F 0.6931471805599453f

__device__ float g_logZ[BB];
__device__ float g_num[BB];

union F4U { float4 v; struct { unsigned long long p01, p23; } u; };

__device__ __forceinline__ unsigned long long ffma2(unsigned long long a,
                                                    unsigned long long b,
                                                    unsigned long long c) {
    unsigned long long d;
    asm("fma.rn.f32x2 %0, %1, %2, %3;" : "=l"(d) : "l"(a), "l"(b), "l"(c));
    return d;
}
__device__ __forceinline__ unsigned long long packf2(float lo, float hi) {
    unsigned long long r;
    asm("mov.b64 %0, {%1,%2};" : "=l"(r) : "f"(lo), "f"(hi));
    return r;
}
__device__ __forceinline__ float2 unpackf2(unsigned long long v) {
    float2 f;
    asm("mov.b64 {%0,%1}, %2;" : "=f"(f.x), "=f"(f.y) : "l"(v));
    return f;
}

// Org: 8 warps, 2 batches. Lane: jq = lane>>3 (j-quarter), kidx = lane&7,
// k0 = w*16 + kidx*2. Lane tile: 32j x 2k x 2b = 64 FFMA2/step. E: 32 u64 regs.
// Epilogue: lane finalizes ONE element (batch ab=jq&1, tag myk=k0+(jq>>1)).
__global__ __launch_bounds__(NTHREADS, 2)
void crf_forward(const float* __restrict__ emissions,
                 const int* __restrict__ mask,
                 const float* __restrict__ start_t,
                 const float* __restrict__ end_t,
                 const float* __restrict__ trans)
{
    __shared__ __align__(16) float sP[2][NBC][PB];   // [ping][b][k padded by quarter]
    __shared__ __align__(16) float sZf[NBC][TT];
    __shared__ int sEa[NBC];

    const int tid  = threadIdx.x;
    const int w    = tid >> 5;
    const int lane = tid & 31;
    const int jq   = lane >> 3;
    const int kidx = lane & 7;
    const int k0   = w * 16 + kidx * 2;
    const int ab   = jq & 1;            // assigned local batch
    const int ak   = jq >> 1;           // assigned k within pair
    const int myk  = k0 + ak;
    const int gba  = blockIdx.x * NBC + ab;     // assigned global batch
    const int kaM  = (myk >> 5) * PQ + (myk & 31);  // padded addr of myk
    const int jb   = jq * PQ;                       // padded addr of lane's j-quarter

    // ---- E: 32 j x 2 k per lane, register-resident (32 u64) ----
    unsigned long long eR[8][2][2];
    #pragma unroll
    for (int t = 0; t < 8; ++t) {
        #pragma unroll
        for (int sub = 0; sub < 2; ++sub) {
            int j = jq * 32 + t * 4 + sub * 2;
            eR[t][sub][0] = packf2(__expf(trans[j * TT + k0]),
                                   __expf(trans[(j + 1) * TT + k0]));
            eR[t][sub][1] = packf2(__expf(trans[j * TT + k0 + 1]),
                                   __expf(trans[(j + 1) * TT + k0 + 1]));
        }
    }

    // ---- init: p~0[ab][myk] ----
    sP[0][ab][kaM] = __expf(start_t[myk] + emissions[(size_t)gba * TT + myk]);
    __syncthreads();

    int cur = 0;
    int e_acc = 0;

    // one-step-ahead prefetch of this lane's emission/mask
    float em = emissions[((size_t)1 * BB + gba) * TT + myk];
    int   m  = mask[1 * BB + gba];

    for (int i = 1; i < LL; ++i) {
        const float* P0 = &sP[cur][0][0];
        const float* P1 = &sP[cur][1][0];

        // prologue (off critical path): est-based exact 2^-e scale for MY batch
        const float4 ev = *(const float4*)&sP[cur][ab][0];
        float s  = (ev.x + ev.y) + (ev.z + ev.w);
        int   es = ((__float_as_int(s) >> 23) & 255) - 126;
        float factor = __expf(em) * __int_as_float((127 - es) << 23);
        float oldp = sP[cur][ab][kaM];

        // prefetch next step
        int inx = (i + 1 < LL) ? i + 1 : LL - 1;
        float nem = emissions[((size_t)inx * BB + gba) * TT + myk];
        int   nm  = mask[inx * BB + gba];

        // ---- contraction: 4 chains (2 b x 2 k), depth 16 ----
        unsigned long long a00 = 0, a01 = 0, a10 = 0, a11 = 0;
        #pragma unroll
        for (int t = 0; t < 8; ++t) {
            F4U p0; p0.v = *(const float4*)(P0 + jb + t * 4);
            F4U p1; p1.v = *(const float4*)(P1 + jb + t * 4);
            a00 = ffma2(p0.u.p01, eR[t][0][0], a00);
            a01 = ffma2(p0.u.p01, eR[t][0][1], a01);
            a10 = ffma2(p1.u.p01, eR[t][0][0], a10);
            a11 = ffma2(p1.u.p01, eR[t][0][1], a11);
            a00 = ffma2(p0.u.p23, eR[t][1][0], a00);
            a01 = ffma2(p0.u.p23, eR[t][1][1], a01);
            a10 = ffma2(p1.u.p23, eR[t][1][0], a10);
            a11 = ffma2(p1.u.p23, eR[t][1][1], a11);
        }
        float2 h;
        h = unpackf2(a00); float f00 = h.x + h.y;
        h = unpackf2(a01); float f01 = h.x + h.y;
        h = unpackf2(a10); float f10 = h.x + h.y;
        h = unpackf2(a11); float f11 = h.x + h.y;
        f00 += __shfl_xor_sync(0xffffffffu, f00, 8);
        f01 += __shfl_xor_sync(0xffffffffu, f01, 8);
        f10 += __shfl_xor_sync(0xffffffffu, f10, 8);
        f11 += __shfl_xor_sync(0xffffffffu, f11, 8);
        f00 += __shfl_xor_sync(0xffffffffu, f00, 16);
        f01 += __shfl_xor_sync(0xffffffffu, f01, 16);
        f10 += __shfl_xor_sync(0xffffffffu, f10, 16);
        f11 += __shfl_xor_sync(0xffffffffu, f11, 16);

        // lane's element: batch ab, k offset ak
        float mine = ab ? (ak ? f11 : f10) : (ak ? f01 : f00);

        float outv;
        if (m) { outv = mine * factor; e_acc += es; }
        else   { outv = oldp; }
        sP[cur ^ 1][ab][kaM] = outv;

        em = nem; m = nm;

        __syncthreads();
        cur ^= 1;
    }

    // ---- finalize ----
    sZf[ab][myk] = sP[cur][ab][kaM] * __expf(end_t[myk]);
    if (w == 0 && kidx == 0 && jq < 2) sEa[jq] = e_acc;   // jq==ab here
    __syncthreads();
    if (w == 0) {
        #pragma unroll
        for (int b = 0; b < NBC; ++b) {
            float v = sZf[b][lane] + sZf[b][lane + 32]
                    + sZf[b][lane + 64] + sZf[b][lane + 96];
            v += __shfl_xor_sync(0xffffffffu, v, 1);
            v += __shfl_xor_sync(0xffffffffu, v, 2);
            v += __shfl_xor_sync(0xffffffffu, v, 4);
            v += __shfl_xor_sync(0xffffffffu, v, 8);
            v += __shfl_xor_sync(0xffffffffu, v, 16);
            if (lane == 0)
                g_logZ[blockIdx.x * NBC + b] = (float)sEa[b] * LN2F + logf(v);
        }
    }
}

// Numerator: one block per batch.
__global__ void crf_num(const float* __restrict__ emissions,
                        const int*   __restrict__ tags,
                        const int*   __restrict__ mask,
                        const float* __restrict__ start_t,
                        const float* __restrict__ end_t,
                        const float* __restrict__ trans)
{
    const int b   = blockIdx.x;
    const int tid = threadIdx.x;
    __shared__ float rf[256];
    __shared__ int   ri[256];

    float loc = 0.f;
    int   cnt = 0;
    for (int i = tid; i < LL; i += 256) {
        int tag = tags[i * BB + b];
        int m   = mask[i * BB + b];
        if (m) {
            loc += emissions[((size_t)i * BB + b) * TT + tag];
            cnt++;
            if (i > 0) loc += trans[tags[(i - 1) * BB + b] * TT + tag];
        }
        if (i == 0) loc += start_t[tag];
    }
    rf[tid] = loc; ri[tid] = cnt;
    __syncthreads();
    #pragma unroll
    for (int s = 128; s > 0; s >>= 1) {
        if (tid < s) { rf[tid] += rf[tid + s]; ri[tid] += ri[tid + s]; }
        __syncthreads();
    }
    if (tid == 0) {
        int ends = ri[0] - 1;
        if (ends < 0) ends = 0;
        g_num[b] = rf[0] + end_t[tags[ends * BB + b]];
    }
}

__global__ void crf_final(float* __restrict__ out)
{
    __shared__ float r[512];
    const int tid = threadIdx.x;
    r[tid] = g_logZ[tid] - g_num[tid];
    __syncthreads();
    #pragma unroll
    for (int s = 256; s > 0; s >>= 1) {
        if (tid < s) r[tid] += r[tid + s];
        __syncthreads();
    }
    if (tid == 0) out[0] = r[0] * (1.0f / (float)BB);
}

extern "C" void kernel_launch(void* const* d_in, const int* in_sizes, int n_in,
                              void* d_out, int out_size)
{
    const float* emissions = (const float*)d_in[0];
    const int*   tags      = (const int*)d_in[1];
    const int*   mask      = (const int*)d_in[2];
    const float* start_t   = (const float*)d_in[3];
    const float* end_t     = (const float*)d_in[4];
    const float* trans     = (const float*)d_in[5];
    float*       out       = (float*)d_out;

    crf_forward<<<NCTA, NTHREADS>>>(emissions, mask, start_t, end_t, trans);
    crf_num<<<BB, 256>>>(emissions, tags, mask, start_t, end_t, trans);
    crf_final<<<1, BB>>>(out);
}